// round 12
// baseline (speedup 1.0000x reference)
#include <cuda_runtime.h>
#include <cuda_bf16.h>

// Problem constants
#define BATCH 16
#define NPTS 2048
#define NUM_CLASSES 40
#define THREADS 256
#define QPB 256                      // queries per block (1 per thread)
#define NCHUNK (NPTS / QPB)          // 8
#define NBLOCKS (2 * BATCH * NCHUNK) // 256
#define NB 64                        // z-buckets
#define ZMIN (-4.5f)
#define HBUK (9.0f / NB)             // 0.140625
#define INVH (NB / 9.0f)
#define MAXPAIRS (NPTS / 2 + NB)     // 1088 (pair-padded buckets)

// Deterministic scratch (no device allocation allowed)
__device__ float g_partials[NBLOCKS];
__device__ int   g_count = 0;   // self-resetting completion counter

// Packed f32x2 helpers (sm_103a FFMA2 — only reachable via PTX)
#define FMA2(acc, a, b) \
    asm("fma.rn.f32x2 %0, %1, %2, %0;" : "+l"(acc) : "l"(a), "l"(b))
#define FMA2_3(dst, a, b, c) \
    asm("fma.rn.f32x2 %0, %1, %2, %3;" : "=l"(dst) : "l"(a), "l"(b), "l"(c))
#define PACK_REP(dst, s) \
    asm("mov.b64 %0, {%1, %1};" : "=l"(dst) : "f"(s))
#define UNPACK2(lo, hi, src) \
    asm("mov.b64 {%0, %1}, %2;" : "=f"(lo), "=f"(hi) : "l"(src))

__device__ __forceinline__ int bucket_of(float z) {
    int b = (int)((z - ZMIN) * INVH);
    return b < 0 ? 0 : (b > NB - 1 ? NB - 1 : b);
}

// Exact z-pruned chamfer. One block: (direction, batch, chunk-of-256-queries).
// Targets bucketed by z into pair-interleaved SMEM buckets; queries bucket-
// sorted by z (deterministic rank via __match_any_sync) so each warp's 32
// lanes hold z-adjacent queries. Warp expands a bucket window outward,
// stopping when the bucket-edge |dz|^2 exceeds every lane's current min
// distance^2 (|dz| <= ||d|| ==> exact nearest neighbor guaranteed).
// All mins exact, scatter deterministic => bitwise-stable across replays.
__global__ __launch_bounds__(THREADS)
void chamfer_kernel(const float* __restrict__ reg,
                    const float* __restrict__ p1,
                    const float* __restrict__ pred,
                    const int*   __restrict__ target32,
                    float* __restrict__ out) {
    __shared__ float4 sTA[MAXPAIRS];   // (x0,x1,y0,y1) per target pair  17 KB
    __shared__ float4 sTB[MAXPAIRS];   // (z0,z1,w0,w1) per target pair  17 KB
    __shared__ float4 sQ[QPB];         // sorted queries (x,y,z,n)        4 KB
    __shared__ int    cnt[NB];
    __shared__ int    fill[NB];
    __shared__ int    pstart[NB + 1];  // bucket starts in PAIR units
    __shared__ int    qcnt[8][NB];     // per-warp per-bucket query counts/offsets
    __shared__ float  sred[THREADS];
    __shared__ int    s_last;

    const int blk   = blockIdx.x;
    const int dir   = blk >> 7;          // 256 blocks: bit 7 = direction
    const int rem   = blk & 127;
    const int b     = rem >> 3;
    const int chunk = rem & 7;
    const int tid   = threadIdx.x;
    const int wid   = tid >> 5;
    const int lane  = tid & 31;

    const float* __restrict__ xsrc = dir ? p1 : reg;
    const float* __restrict__ ysrc = dir ? reg : p1;
    const float* xb = xsrc + (size_t)b * NPTS * 3;
    const float* yb = ysrc + (size_t)b * NPTS * 3;

    // ---- Phase 0: zero counters ----
    if (tid < NB) { cnt[tid] = 0; fill[tid] = 0; }
    for (int k = tid; k < 8 * NB; k += THREADS) ((int*)qcnt)[k] = 0;
    __syncthreads();

    // ---- Phase 1: target z-histogram (8 targets/thread) ----
    #pragma unroll
    for (int k = 0; k < NPTS / THREADS; k++) {
        const int i = tid + THREADS * k;
        atomicAdd(&cnt[bucket_of(yb[i * 3 + 2])], 1);
    }

    // Query: load, bucket, deterministic warp-rank
    const int qi = chunk * QPB + tid;
    const float qx = xb[qi * 3 + 0], qy = xb[qi * 3 + 1], qzv = xb[qi * 3 + 2];
    const float qn = qx * qx + qy * qy + qzv * qzv;
    const int qbk = bucket_of(qzv);
    const unsigned msk  = __match_any_sync(0xFFFFFFFFu, qbk);
    const int      rank = __popc(msk & ((1u << lane) - 1u));
    if (rank == 0) qcnt[wid][qbk] = __popc(msk);
    __syncthreads();

    // ---- Phase 2: serial prefixes (tiny; tid 0) ----
    if (tid == 0) {
        int run = 0;
        #pragma unroll 4
        for (int B = 0; B < NB; B++) { pstart[B] = run; run += (cnt[B] + 1) >> 1; }
        pstart[NB] = run;
        int qrun = 0;
        for (int B = 0; B < NB; B++)
            for (int w = 0; w < 8; w++) { int t = qcnt[w][B]; qcnt[w][B] = qrun; qrun += t; }
    }
    __syncthreads();

    // ---- Phase 3: sentinel-init pairs; deterministic query scatter ----
    const int totP = pstart[NB];
    for (int j = tid; j < totP; j += THREADS) {
        sTA[j] = make_float4(0.f, 0.f, 0.f, 0.f);
        sTB[j] = make_float4(0.f, 0.f, 1e30f, 1e30f);
    }
    sQ[qcnt[wid][qbk] + rank] = make_float4(qx, qy, qzv, qn);
    __syncthreads();

    // ---- Phase 4: target scatter into pair-interleaved buckets ----
    #pragma unroll
    for (int k = 0; k < NPTS / THREADS; k++) {
        const int i = tid + THREADS * k;
        const float tx = yb[i * 3 + 0], ty = yb[i * 3 + 1], tz = yb[i * 3 + 2];
        const float tw = tx * tx + ty * ty + tz * tz;
        const int bb  = bucket_of(tz);
        const int pos = atomicAdd(&fill[bb], 1);
        const int pr  = pstart[bb] + (pos >> 1);
        const int hf  = pos & 1;
        float* A = (float*)&sTA[pr];
        float* Bp = (float*)&sTB[pr];
        A[hf] = tx; A[2 + hf] = ty; Bp[hf] = tz; Bp[2 + hf] = tw;
    }
    __syncthreads();

    // ---- Phase 5: pruned scan. Lane owns sorted query sQ[tid]. ----
    const float4 q = sQ[tid];
    unsigned long long X, Y, Z;
    PACK_REP(X, -2.0f * q.x);
    PACK_REP(Y, -2.0f * q.y);
    PACK_REP(Z, -2.0f * q.z);
    const float qz = q.z, n = q.w;

    const ulonglong2* __restrict__ pTA = reinterpret_cast<const ulonglong2*>(sTA);
    const ulonglong2* __restrict__ pTB = reinterpret_cast<const ulonglong2*>(sTB);

    float ma = 3.0e38f, mb = 3.0e38f;   // split min accumulators of d' = d^2 - n

    #define PROCESS_BUCKET(B) do {                                         \
        const int _p1 = pstart[(B) + 1];                                   \
        for (int j = pstart[(B)]; j < _p1; j++) {                          \
            const ulonglong2 qa = pTA[j];                                  \
            const ulonglong2 qb = pTB[j];                                  \
            unsigned long long t;                                          \
            FMA2_3(t, Z, qb.x, qb.y);                                      \
            FMA2(t, Y, qa.y);                                              \
            FMA2(t, X, qa.x);                                              \
            float lov, hiv; UNPACK2(lov, hiv, t);                          \
            ma = fminf(ma, lov); mb = fminf(mb, hiv);                      \
        } } while (0)

    int c = bucket_of(qz);
    int lo = c, hi = c;
    #pragma unroll
    for (int off = 16; off > 0; off >>= 1) {
        lo = min(lo, __shfl_xor_sync(0xFFFFFFFFu, lo, off));
        hi = max(hi, __shfl_xor_sync(0xFFFFFFFFu, hi, off));
    }
    for (int B = lo; B <= hi; B++) PROCESS_BUCKET(B);

    for (int iter = 0; iter < NB; iter++) {
        const float thr = n + fminf(ma, mb);   // current min distance^2
        bool vLo = (lo > 0);
        if (vLo) { const float dz = qz - (ZMIN + lo * HBUK); vLo = dz * dz < thr; }
        bool vHi = (hi < NB - 1);
        if (vHi) { const float dz = (ZMIN + (hi + 1) * HBUK) - qz; vHi = dz * dz < thr; }
        const bool aLo = __any_sync(0xFFFFFFFFu, vLo);
        const bool aHi = __any_sync(0xFFFFFFFFu, vHi);
        if (!aLo && !aHi) break;
        if (aLo) { lo--; PROCESS_BUCKET(lo); }
        if (aHi) { hi++; PROCESS_BUCKET(hi); }
    }
    #undef PROCESS_BUCKET

    // ---- Reduction: exact per-query min + n, block tree-sum ----
    sred[tid] = n + fminf(ma, mb);
    __syncthreads();
    #pragma unroll
    for (int off = THREADS / 2; off >= 32; off >>= 1) {
        if (tid < off) sred[tid] += sred[tid + off];
        __syncthreads();
    }
    if (tid < 32) {
        float v = sred[tid];
        #pragma unroll
        for (int off = 16; off > 0; off >>= 1)
            v += __shfl_down_sync(0xFFFFFFFFu, v, off);
        if (tid == 0) g_partials[blk] = v;
    }

    // ---- Fused finalize: last block sums partials + NLL ----
    if (tid == 0) {
        __threadfence();
        const int r = atomicAdd(&g_count, 1);
        s_last = (r == NBLOCKS - 1);
    }
    __syncthreads();
    if (!s_last) return;
    __threadfence();   // acquire other blocks' partials

    {
        volatile float* vp = g_partials;
        sred[tid] = vp[tid];   // NBLOCKS == THREADS
    }
    __syncthreads();
    #pragma unroll
    for (int off = THREADS / 2; off >= 32; off >>= 1) {
        if (tid < off) sred[tid] += sred[tid + off];
        __syncthreads();
    }
    if (tid < 32) {
        float w = sred[tid];
        #pragma unroll
        for (int off = 16; off > 0; off >>= 1)
            w += __shfl_down_sync(0xFFFFFFFFu, w, off);
        if (tid == 0) {
            const float reg_loss = w / (float)(BATCH * NPTS);

            // dtype sniff: JAX x64-disabled emits int32 despite declared int64.
            bool is64 = true;
            #pragma unroll
            for (int i = 0; i < 8; i++)
                if (target32[2 * i + 1] != 0) is64 = false;

            float nll = 0.0f;
            #pragma unroll
            for (int i = 0; i < BATCH; i++) {
                int t = is64 ? target32[2 * i] : target32[i];
                t = (t < 0) ? 0 : (t >= NUM_CLASSES ? NUM_CLASSES - 1 : t);
                nll -= pred[i * NUM_CLASSES + t];
            }
            nll /= (float)BATCH;
            out[0] = nll + reg_loss;
            g_count = 0;   // self-reset for next graph replay
        }
    }
}

extern "C" void kernel_launch(void* const* d_in, const int* in_sizes, int n_in,
                              void* d_out, int out_size) {
    const float* reg    = (const float*)d_in[0];   // [16, 2048, 3]
    const float* p1     = (const float*)d_in[1];   // [16, 2048, 3]
    const float* pred   = (const float*)d_in[2];   // [16, 40] log-probs
    const int*   target = (const int*)d_in[3];     // [16] int32 (or int64, sniffed)
    float* out = (float*)d_out;

    chamfer_kernel<<<NBLOCKS, THREADS>>>(reg, p1, pred, target, out);
}

// round 13
// speedup vs baseline: 1.1320x; 1.1320x over previous
#include <cuda_runtime.h>
#include <cuda_bf16.h>

// Problem constants
#define BATCH 16
#define NPTS 2048
#define NUM_CLASSES 40
#define THREADS 256
#define QPB 256                      // queries per block (1 per thread)
#define NCHUNK (NPTS / QPB)          // 8
#define NBLOCKS (2 * BATCH * NCHUNK) // 256
#define NB 64                        // z-buckets
#define ZMIN (-3.5f)
#define ZRANGE 7.0f
#define HBUK (ZRANGE / NB)           // 0.109375
#define INVH (NB / ZRANGE)
#define MAXPAIRS (NPTS / 2 + NB)     // 1088 (pair-padded buckets)
#define TPT (NPTS / THREADS)         // 8 targets per thread

// Deterministic scratch (no device allocation allowed)
__device__ float g_partials[NBLOCKS];
__device__ int   g_count = 0;   // self-resetting completion counter

// Packed f32x2 helpers (sm_103a FFMA2 — only reachable via PTX)
#define FMA2(acc, a, b) \
    asm("fma.rn.f32x2 %0, %1, %2, %0;" : "+l"(acc) : "l"(a), "l"(b))
#define FMA2_3(dst, a, b, c) \
    asm("fma.rn.f32x2 %0, %1, %2, %3;" : "=l"(dst) : "l"(a), "l"(b), "l"(c))
#define PACK_REP(dst, s) \
    asm("mov.b64 %0, {%1, %1};" : "=l"(dst) : "f"(s))
#define UNPACK2(lo, hi, src) \
    asm("mov.b64 {%0, %1}, %2;" : "=f"(lo), "=f"(hi) : "l"(src))

__device__ __forceinline__ int bucket_of(float z) {
    int b = (int)((z - ZMIN) * INVH);
    return b < 0 ? 0 : (b > NB - 1 ? NB - 1 : b);
}

// Exact z-pruned chamfer (R12 algorithm, de-serialized):
// parallel shuffle-scans replace the tid0 serial prefix; bucket loop is
// manually unrolled 2x (two independent LDS->FFMA2 chains per iteration).
// Clamped edge buckets keep the |dz| bound exact (clamped points lie beyond
// the tested bucket edge). Query->lane map fully deterministic.
__global__ __launch_bounds__(THREADS)
void chamfer_kernel(const float* __restrict__ reg,
                    const float* __restrict__ p1,
                    const float* __restrict__ pred,
                    const int*   __restrict__ target32,
                    float* __restrict__ out) {
    __shared__ float4 sTA[MAXPAIRS];   // (x0,x1,y0,y1) per target pair
    __shared__ float4 sTB[MAXPAIRS];   // (z0,z1,w0,w1) per target pair
    __shared__ float4 sQ[QPB];         // sorted queries (x,y,z,n)
    __shared__ int    cnt[NB];
    __shared__ int    fill[NB];
    __shared__ int    pstart[NB + 1];  // bucket starts in PAIR units
    __shared__ int    qc[8][NB];       // per-warp per-bucket query counts
    __shared__ int    qtot[NB];
    __shared__ int    qstart[NB];      // exclusive starts of query buckets
    __shared__ float  sred[THREADS];
    __shared__ int    s_last;

    const int blk   = blockIdx.x;
    const int dir   = blk >> 7;          // 256 blocks: bit 7 = direction
    const int rem   = blk & 127;
    const int b     = rem >> 3;
    const int chunk = rem & 7;
    const int tid   = threadIdx.x;
    const int wid   = tid >> 5;
    const int lane  = tid & 31;

    const float* __restrict__ xsrc = dir ? p1 : reg;
    const float* __restrict__ ysrc = dir ? reg : p1;
    const float* xb = xsrc + (size_t)b * NPTS * 3;
    const float* yb = ysrc + (size_t)b * NPTS * 3;

    // ---- Phase 0: zero counters ----
    if (tid < NB) { cnt[tid] = 0; fill[tid] = 0; }
    for (int k = tid; k < 8 * NB; k += THREADS) ((int*)qc)[k] = 0;
    __syncthreads();

    // ---- Phase 1: target z-histogram; cache z + bucket in registers ----
    float tzs[TPT];
    int   tbk[TPT];
    #pragma unroll
    for (int k = 0; k < TPT; k++) {
        const int i = tid + THREADS * k;
        tzs[k] = yb[i * 3 + 2];
        tbk[k] = bucket_of(tzs[k]);
        atomicAdd(&cnt[tbk[k]], 1);
    }

    // Query: load, bucket, deterministic warp-rank
    const int qi = chunk * QPB + tid;
    const float qx = xb[qi * 3 + 0], qy = xb[qi * 3 + 1], qzv = xb[qi * 3 + 2];
    const float qn = qx * qx + qy * qy + qzv * qzv;
    const int qbk = bucket_of(qzv);
    const unsigned msk  = __match_any_sync(0xFFFFFFFFu, qbk);
    const int      rank = __popc(msk & ((1u << lane) - 1u));
    if (rank == 0) qc[wid][qbk] = __popc(msk);
    __syncthreads();

    // ---- Phase 2a: per-bucket query totals (64 threads, 8 adds each) ----
    if (tid < NB) {
        int s = 0;
        #pragma unroll
        for (int w = 0; w < 8; w++) s += qc[w][tid];
        qtot[tid] = s;
    }
    __syncthreads();

    // ---- Phase 2b: dual parallel scans in warp 0 (2 buckets per lane) ----
    if (tid < 32) {
        // pair counts scan
        const int c0 = cnt[2 * tid], c1 = cnt[2 * tid + 1];
        const int pc0 = (c0 + 1) >> 1, pc1 = (c1 + 1) >> 1;
        int s = pc0 + pc1;
        int inc = s;
        #pragma unroll
        for (int off = 1; off < 32; off <<= 1) {
            const int t = __shfl_up_sync(0xFFFFFFFFu, inc, off);
            if (lane >= off) inc += t;
        }
        pstart[2 * tid]     = inc - s;
        pstart[2 * tid + 1] = inc - pc1;
        if (tid == 31) pstart[NB] = inc;

        // query counts scan
        const int q0 = qtot[2 * tid], q1 = qtot[2 * tid + 1];
        int s2 = q0 + q1;
        int inc2 = s2;
        #pragma unroll
        for (int off = 1; off < 32; off <<= 1) {
            const int t = __shfl_up_sync(0xFFFFFFFFu, inc2, off);
            if (lane >= off) inc2 += t;
        }
        qstart[2 * tid]     = inc2 - s2;
        qstart[2 * tid + 1] = inc2 - q1;
    }
    __syncthreads();

    // ---- Phase 3: sentinel-init pairs; deterministic query scatter ----
    const int totP = pstart[NB];
    for (int j = tid; j < totP; j += THREADS) {
        sTA[j] = make_float4(0.f, 0.f, 0.f, 0.f);
        sTB[j] = make_float4(0.f, 0.f, 1e30f, 1e30f);
    }
    {
        int woff = 0;
        for (int w = 0; w < wid; w++) woff += qc[w][qbk];
        sQ[qstart[qbk] + woff + rank] = make_float4(qx, qy, qzv, qn);
    }
    __syncthreads();

    // ---- Phase 4: target scatter into pair-interleaved buckets ----
    // (fill order nondeterministic but min over a bucket is order-invariant)
    #pragma unroll
    for (int k = 0; k < TPT; k++) {
        const int i = tid + THREADS * k;
        const float tx = yb[i * 3 + 0], ty = yb[i * 3 + 1], tz = tzs[k];
        const float tw = tx * tx + ty * ty + tz * tz;
        const int bb  = tbk[k];
        const int pos = atomicAdd(&fill[bb], 1);
        const int pr  = pstart[bb] + (pos >> 1);
        const int hf  = pos & 1;
        float* A  = (float*)&sTA[pr];
        float* Bp = (float*)&sTB[pr];
        A[hf] = tx; A[2 + hf] = ty; Bp[hf] = tz; Bp[2 + hf] = tw;
    }
    __syncthreads();

    // ---- Phase 5: pruned scan. Lane owns sorted query sQ[tid]. ----
    const float4 q = sQ[tid];
    unsigned long long X, Y, Z;
    PACK_REP(X, -2.0f * q.x);
    PACK_REP(Y, -2.0f * q.y);
    PACK_REP(Z, -2.0f * q.z);
    const float qz = q.z, n = q.w;

    const ulonglong2* __restrict__ pTA = reinterpret_cast<const ulonglong2*>(sTA);
    const ulonglong2* __restrict__ pTB = reinterpret_cast<const ulonglong2*>(sTB);

    float ma = 3.0e38f, mb = 3.0e38f;   // split min accumulators of d^2 - n

    #define PROCESS_BUCKET(B) do {                                          \
        int _j = pstart[(B)];                                               \
        const int _e = pstart[(B) + 1];                                     \
        for (; _j + 2 <= _e; _j += 2) {                                     \
            const ulonglong2 a0 = pTA[_j],     b0 = pTB[_j];                \
            const ulonglong2 a1 = pTA[_j + 1], b1 = pTB[_j + 1];            \
            unsigned long long t0, t1;                                      \
            FMA2_3(t0, Z, b0.x, b0.y);  FMA2_3(t1, Z, b1.x, b1.y);          \
            FMA2(t0, Y, a0.y);          FMA2(t1, Y, a1.y);                  \
            FMA2(t0, X, a0.x);          FMA2(t1, X, a1.x);                  \
            float l0, h0, l1, h1;                                           \
            UNPACK2(l0, h0, t0); UNPACK2(l1, h1, t1);                       \
            ma = fminf(ma, fminf(l0, l1));                                  \
            mb = fminf(mb, fminf(h0, h1));                                  \
        }                                                                   \
        if (_j < _e) {                                                      \
            const ulonglong2 a0 = pTA[_j], b0 = pTB[_j];                    \
            unsigned long long t0;                                          \
            FMA2_3(t0, Z, b0.x, b0.y);                                      \
            FMA2(t0, Y, a0.y);                                              \
            FMA2(t0, X, a0.x);                                              \
            float l0, h0; UNPACK2(l0, h0, t0);                              \
            ma = fminf(ma, l0); mb = fminf(mb, h0);                         \
        } } while (0)

    int lo = bucket_of(qz), hi = lo;
    #pragma unroll
    for (int off = 16; off > 0; off >>= 1) {
        lo = min(lo, __shfl_xor_sync(0xFFFFFFFFu, lo, off));
        hi = max(hi, __shfl_xor_sync(0xFFFFFFFFu, hi, off));
    }
    for (int B = lo; B <= hi; B++) PROCESS_BUCKET(B);

    for (int iter = 0; iter < NB; iter++) {
        const float thr = n + fminf(ma, mb);   // current min distance^2
        bool vLo = (lo > 0);
        if (vLo) { const float dz = qz - (ZMIN + lo * HBUK); vLo = dz * dz < thr; }
        bool vHi = (hi < NB - 1);
        if (vHi) { const float dz = (ZMIN + (hi + 1) * HBUK) - qz; vHi = dz * dz < thr; }
        const bool aLo = __any_sync(0xFFFFFFFFu, vLo);
        const bool aHi = __any_sync(0xFFFFFFFFu, vHi);
        if (!aLo && !aHi) break;
        if (aLo) { lo--; PROCESS_BUCKET(lo); }
        if (aHi) { hi++; PROCESS_BUCKET(hi); }
    }
    #undef PROCESS_BUCKET

    // ---- Reduction: exact per-query min + n, block tree-sum ----
    sred[tid] = n + fminf(ma, mb);
    __syncthreads();
    #pragma unroll
    for (int off = THREADS / 2; off >= 32; off >>= 1) {
        if (tid < off) sred[tid] += sred[tid + off];
        __syncthreads();
    }
    if (tid < 32) {
        float v = sred[tid];
        #pragma unroll
        for (int off = 16; off > 0; off >>= 1)
            v += __shfl_down_sync(0xFFFFFFFFu, v, off);
        if (tid == 0) g_partials[blk] = v;
    }

    // ---- Fused finalize: last block sums partials + NLL ----
    if (tid == 0) {
        __threadfence();
        const int r = atomicAdd(&g_count, 1);
        s_last = (r == NBLOCKS - 1);
    }
    __syncthreads();
    if (!s_last) return;
    __threadfence();   // acquire other blocks' partials

    {
        volatile float* vp = g_partials;
        sred[tid] = vp[tid];   // NBLOCKS == THREADS
    }
    __syncthreads();
    #pragma unroll
    for (int off = THREADS / 2; off >= 32; off >>= 1) {
        if (tid < off) sred[tid] += sred[tid + off];
        __syncthreads();
    }
    if (tid < 32) {
        float w = sred[tid];
        #pragma unroll
        for (int off = 16; off > 0; off >>= 1)
            w += __shfl_down_sync(0xFFFFFFFFu, w, off);
        if (tid == 0) {
            const float reg_loss = w / (float)(BATCH * NPTS);

            // dtype sniff: JAX x64-disabled emits int32 despite declared int64.
            bool is64 = true;
            #pragma unroll
            for (int i = 0; i < 8; i++)
                if (target32[2 * i + 1] != 0) is64 = false;

            float nll = 0.0f;
            #pragma unroll
            for (int i = 0; i < BATCH; i++) {
                int t = is64 ? target32[2 * i] : target32[i];
                t = (t < 0) ? 0 : (t >= NUM_CLASSES ? NUM_CLASSES - 1 : t);
                nll -= pred[i * NUM_CLASSES + t];
            }
            nll /= (float)BATCH;
            out[0] = nll + reg_loss;
            g_count = 0;   // self-reset for next graph replay
        }
    }
}

extern "C" void kernel_launch(void* const* d_in, const int* in_sizes, int n_in,
                              void* d_out, int out_size) {
    const float* reg    = (const float*)d_in[0];   // [16, 2048, 3]
    const float* p1     = (const float*)d_in[1];   // [16, 2048, 3]
    const float* pred   = (const float*)d_in[2];   // [16, 40] log-probs
    const int*   target = (const int*)d_in[3];     // [16] int32 (or int64, sniffed)
    float* out = (float*)d_out;

    chamfer_kernel<<<NBLOCKS, THREADS>>>(reg, p1, pred, target, out);
}